// round 14
// baseline (speedup 1.0000x reference)
#include <cuda_runtime.h>
#include <cuda_bf16.h>
#include <cooperative_groups.h>

namespace cg = cooperative_groups;

// Problem constants (pinned by the reference)
#define B_DIM   64
#define S_DIM   8192
#define D_DIM   64
#define N_BINS  256                 // output bins; bin 256 = dummy (T >= 256)
#define NCHUNK  4                   // CTAs (cluster size) per batch in the sort
#define CHUNK_S (S_DIM / NCHUNK)    // 2048 tokens per chunk
#define NBIN1   (N_BINS + 1)        // 257 (incl. dummy)
#define STARTS_PER_B 258

#define BINS_PER_CTA 8              // K2: one warp per bin, 8 bins per CTA
#define STAGE_CAP    1024           // smem (x,w) slots per CTA (8 KB); E[need]=256

// Scratch (allocation-free rule: __device__ globals)
__device__ int2 g_sorted[B_DIM * S_DIM];          // (x, w-bits), bin-contiguous per batch
__device__ int  g_start [B_DIM * STARTS_PER_B];   // per-batch exclusive bin starts

// ---------------------------------------------------------------------------
// K1: fused per-batch counting sort, SINGLE atomic pass. (FROZEN: best
// measured config, ~5.1-5.3 us. The atomicAdd return value doubles as the
// within-bin rank, making the local scatter atomic-free.)
// ---------------------------------------------------------------------------
__global__ __launch_bounds__(512, 2) __cluster_dims__(NCHUNK, 1, 1)
void k_sort(const float* __restrict__ T, const int* __restrict__ X,
            const float* __restrict__ embedW)
{
    __shared__ int            hist [NBIN1];
    __shared__ int            scanT[NBIN1];    // batch-wide totals (scanned)
    __shared__ int            scanL[NBIN1];    // own-chunk hist (scanned)
    __shared__ int            delta[NBIN1];    // p_local + delta[bin] = global pos
    __shared__ int            lbase[NBIN1];    // local (chunk) bin starts
    __shared__ unsigned int   sbr  [CHUNK_S];  // packed (rank<<16 | bin), original order
    __shared__ unsigned short sbin2[CHUNK_S];  // bin at locally-sorted position
    __shared__ int            sx   [CHUNK_S];  // token id at locally-sorted position

    cg::cluster_group cluster = cg::this_cluster();
    const int c   = (int)cluster.block_rank();     // chunk 0..3
    const int b   = blockIdx.x >> 2;               // batch
    const int tid = threadIdx.x;

    for (int i = tid; i < NBIN1; i += 512) hist[i] = 0;
    __syncthreads();

    // --- A: bin + histogram; the atomic's return value IS the rank ---
    const float* Tb = T + b * S_DIM + c * CHUNK_S;
    #pragma unroll 4
    for (int s = tid; s < CHUNK_S; s += 512) {
        float t  = Tb[s];
        int bin  = (t < 256.0f) ? (int)t : N_BINS; // t >= 0 -> (int)t == floor
        int rank = atomicAdd(&hist[bin], 1);
        sbr[s]   = ((unsigned int)rank << 16) | (unsigned int)bin;
    }
    cluster.sync();

    // --- B: peer hist gather + dual scan ---
    int tot = 0, part = 0, own = 0;
    if (tid < NBIN1) {
        #pragma unroll
        for (int cc = 0; cc < NCHUNK; ++cc) {
            const int* rh = cluster.map_shared_rank(hist, cc);
            int h = rh[tid];
            tot += h;
            if (cc < c) part += h;
        }
        own = hist[tid];
        scanT[tid] = tot;
        scanL[tid] = own;
    }
    __syncthreads();

    for (int d = 1; d < NBIN1; d <<= 1) {
        int vT = 0, vL = 0;
        if (tid < NBIN1 && tid >= d) { vT = scanT[tid - d]; vL = scanL[tid - d]; }
        __syncthreads();
        if (tid < NBIN1) { scanT[tid] += vT; scanL[tid] += vL; }
        __syncthreads();
    }

    if (tid < NBIN1) {
        int gbase  = scanT[tid] - tot;   // batch-wide bin start
        int lb     = scanL[tid] - own;   // local (chunk) bin start
        lbase[tid] = lb;
        delta[tid] = gbase + part - lb;
        if (c == 0) {
            g_start[b * STARTS_PER_B + tid] = gbase;
            if (tid == 0) g_start[b * STARTS_PER_B + NBIN1] = S_DIM;
        }
    }
    __syncthreads();

    // --- C: atomic-free local scatter (position = lbase[bin] + rank) ---
    const int* Xb = X + b * S_DIM + c * CHUNK_S;
    #pragma unroll 4
    for (int s = tid; s < CHUNK_S; s += 512) {
        unsigned int br = sbr[s];
        int bin  = (int)(br & 0xFFFFu);
        int lpos = lbase[bin] + (int)(br >> 16);
        sx[lpos]    = Xb[s];
        sbin2[lpos] = (unsigned short)bin;
    }
    __syncthreads();

    // --- D: coalesced copy-out + weight compute ---
    int2* dst = g_sorted + b * S_DIM;
    #pragma unroll 4
    for (int p = tid; p < CHUNK_S; p += 512) {
        int   x   = sx[p];
        int   bin = sbin2[p];
        float w   = __expf(__ldg(&embedW[x]));
        dst[p + delta[bin]] = make_int2(x, __float_as_int(w));
    }

    cluster.sync();   // peers may still be reading our smem hist
}

// ---------------------------------------------------------------------------
// K2: R10 config restored EXACTLY (best measured: 16.1 us, occ 75.5%):
// one CTA per (batch, 8 consecutive bins), one warp per bin, contiguous
// (x,w) range staged once into smem, float2 gathers, unroll 4, plain
// 256-thread launch (no min-CTA cap). One addition: a manual next-(x,w)
// register prefetch so the unrolled body's LDGs don't serialize behind
// their own LDS (no change to unroll depth, widths, or register class).
// ---------------------------------------------------------------------------
__global__ __launch_bounds__(256)
void k_bin_reduce(const float* __restrict__ embedX, float* __restrict__ out)
{
    __shared__ int2 stage[STAGE_CAP + 1];   // +1: safe prefetch overread slot
    __shared__ int  sgs[BINS_PER_CTA + 1];

    const int tid  = threadIdx.x;
    const int wid  = tid >> 5;                 // warp in CTA = bin offset 0..7
    const int lane = tid & 31;
    const int b    = blockIdx.x >> 5;          // batch 0..63
    const int bin0 = (blockIdx.x & 31) * BINS_PER_CTA;

    if (tid <= BINS_PER_CTA)
        sgs[tid] = g_start[b * STARTS_PER_B + bin0 + tid];
    if (tid == 0) stage[STAGE_CAP] = make_int2(0, 0);
    __syncthreads();

    const int s0c = sgs[0];
    const int cnt = sgs[BINS_PER_CTA] - s0c;
    const int2* gxw = g_sorted + b * S_DIM + s0c;

    const bool staged = (cnt <= STAGE_CAP);
    if (staged) {
        for (int i = tid; i < cnt; i += 256)
            stage[i] = gxw[i];
    }
    __syncthreads();

    const int s0 = sgs[wid]     - s0c;         // this warp's bin, local offsets
    const int s1 = sgs[wid + 1] - s0c;
    const int n  = s1 - s0;

    const float2* ex = reinterpret_cast<const float2*>(embedX);
    float2 acc = make_float2(0.0f, 0.0f);

    if (staged) {
        int2 xw = stage[s0];                   // prime the pipeline
        #pragma unroll 4
        for (int i = s0; i < s1; ++i) {
            int2 nxt = stage[i + 1];           // prefetch (slot cnt.. is init'd)
            float w  = __int_as_float(xw.y);
            float2 e = __ldg(&ex[xw.x * 32 + lane]);
            acc.x = fmaf(w, e.x, acc.x);
            acc.y = fmaf(w, e.y, acc.y);
            xw = nxt;
        }
    } else {                                    // safety net (never for this input)
        #pragma unroll 4
        for (int i = s0; i < s1; ++i) {
            int2  xw2 = __ldg(&gxw[i]);         // broadcast LDG.64
            float w   = __int_as_float(xw2.y);
            float2 e  = __ldg(&ex[xw2.x * 32 + lane]);
            acc.x = fmaf(w, e.x, acc.x);
            acc.y = fmaf(w, e.y, acc.y);
        }
    }

    float inv = 1.0f / ((float)n + 1e-6f);
    reinterpret_cast<float2*>(out)[(b * N_BINS + bin0 + wid) * 32 + lane] =
        make_float2(acc.x * inv, acc.y * inv);
}

// ---------------------------------------------------------------------------
// Inputs (metadata order):
//   d_in[0] : T        float32 [B, S]
//   d_in[1] : X_ids    int32   [B, S]
//   d_in[2] : embedX_w float32 [N_TOKENS+1, 64]
//   d_in[3] : embedW_w float32 [N_TOKENS+1, 1]
// Output    : float32 [B, 256, 64]
// ---------------------------------------------------------------------------
extern "C" void kernel_launch(void* const* d_in, const int* in_sizes, int n_in,
                              void* d_out, int out_size)
{
    const float* T      = (const float*)d_in[0];
    const int*   X_ids  = (const int*)  d_in[1];
    const float* embedX = (const float*)d_in[2];
    const float* embedW = (const float*)d_in[3];
    float*       out    = (float*)d_out;

    k_sort      <<<B_DIM * NCHUNK, 512>>>(T, X_ids, embedW);
    k_bin_reduce<<<B_DIM * (N_BINS / BINS_PER_CTA), 256>>>(embedX, out);
}